// round 8
// baseline (speedup 1.0000x reference)
#include <cuda_runtime.h>

#define N 384
#define D 512
#define MARGIN 0.5f
#define EPS 1e-6f
#define BLK 384
#define NWARP (BLK / 32)

// Finalize scratch; zero-initialized at load, winner resets each launch so
// graph replays start clean.
__device__ float g_acc;
__device__ int   g_cnt;

__global__ __launch_bounds__(BLK) void triplet_fused_kernel(
    const float* __restrict__ features,
    const int*   __restrict__ labels,
    const int*   __restrict__ levels,
    float*       __restrict__ out) {
    __shared__ float    s_dist[N];            // only same-label entries touched
    __shared__ unsigned s_same_mask[NWARP];
    __shared__ unsigned s_neg_mask[NWARP];
    __shared__ float    s_sum;

    const int i    = blockIdx.x;
    const int t    = threadIdx.x;
    const int wid  = t >> 5;
    const int lane = t & 31;

    if (t == 0) s_sum = 0.0f;

    const int lab_i = labels[i];     // broadcast: one L2 transaction
    const int lev_i = levels[i];
    const int lab_t = labels[t];     // coalesced
    const int lev_t = levels[t];

    const bool same   = (t != i) && (lab_t == lab_i);
    const bool is_pos = same && (lev_t == lev_i);

    const unsigned bal_same = __ballot_sync(0xffffffffu, same);
    const unsigned bal_pos  = __ballot_sync(0xffffffffu, is_pos);
    if (lane == 0) {
        s_same_mask[wid] = bal_same;
        s_neg_mask[wid]  = bal_same & ~bal_pos;
    }
    __syncthreads();                 // ONLY barrier before distances

    // Pull masks into registers; lanes decode ordinals in parallel (once).
    unsigned sm[NWARP];
    int nsame = 0;
#pragma unroll
    for (int w = 0; w < NWARP; w++) { sm[w] = s_same_mask[w]; nsame += __popc(sm[w]); }

    // Lane l decodes the global index of same-label member #l.
    int j_ord = 0;
    {
        int rem = lane;
#pragma unroll
        for (int w = 0; w < NWARP; w++) {
            const int c = __popc(sm[w]);
            if (rem >= 0 && rem < c) j_ord = (w << 5) + __fns(sm[w], 0, rem + 1);
            rem -= c;
        }
    }

    // ---- distances: warps round-robin over ordinals; j via one shfl ----
    const float4* __restrict__ fi = (const float4*)(features + i * D);
    for (int m = wid; m < nsame; m += NWARP) {
        int j;
        if (m < 32) {                       // uniform per warp
            j = __shfl_sync(0xffffffffu, j_ord, m);
        } else {                            // rare: class larger than 32
            int rem = m; j = 0;
#pragma unroll
            for (int w = 0; w < NWARP; w++) {
                const int c = __popc(sm[w]);
                if (rem >= 0 && rem < c) j = (w << 5) + __fns(sm[w], 0, rem + 1);
                rem -= c;
            }
        }
        const float4* __restrict__ fj = (const float4*)(features + j * D);
        float acc = 0.0f;
#pragma unroll
        for (int u = 0; u < 4; u++) {
            const int idx = u * 32 + lane;  // coalesced per warp, MLP=4
            float4 a = fi[idx];
            float4 b = fj[idx];
            float d0 = a.x - b.x + EPS;     // torch pairwise_distance eps
            float d1 = a.y - b.y + EPS;
            float d2 = a.z - b.z + EPS;
            float d3 = a.w - b.w + EPS;
            acc = fmaf(d0, d0, acc);
            acc = fmaf(d1, d1, acc);
            acc = fmaf(d2, d2, acc);
            acc = fmaf(d3, d3, acc);
        }
#pragma unroll
        for (int o = 16; o; o >>= 1) acc += __shfl_xor_sync(0xffffffffu, acc, o);
        if (lane == 0) s_dist[j] = sqrtf(acc);
    }
    __syncthreads();

    // ---- hinge: positive thread t walks the negative bitmasks (~6 iters) ----
    float acc = 0.0f;
    if (is_pos) {
        const float dij = s_dist[t];
#pragma unroll
        for (int w = 0; w < NWARP; w++) {
            unsigned nm = s_neg_mask[w];
            while (nm) {
                const int b = __ffs(nm) - 1;
                nm &= nm - 1;
                acc += fmaxf(dij - s_dist[(w << 5) + b] + MARGIN, 0.0f);
            }
        }
    }
    if (acc != 0.0f) atomicAdd(&s_sum, acc);   // only ~6 threads land here
    __syncthreads();

    // ---- finalize: REDG contribution + ticket; last block writes out ----
    if (t == 0) {
        int nneg = 0;
#pragma unroll
        for (int w = 0; w < NWARP; w++) nneg += __popc(s_neg_mask[w]);
        const int npos = nsame - nneg;
        float contrib = 0.0f;
        if (npos > 0 && nneg > 0)
            contrib = s_sum / (float)(npos * nneg) * (1.0f / (float)N);
        atomicAdd(&g_acc, contrib);            // no return -> REDG
        __threadfence();
        if (atomicAdd(&g_cnt, 1) == (int)gridDim.x - 1) {
            g_cnt = 0;
            out[0] = atomicExch(&g_acc, 0.0f); // read + reset for graph replay
        }
    }
}

extern "C" void kernel_launch(void* const* d_in, const int* in_sizes, int n_in,
                              void* d_out, int out_size) {
    const float* features = (const float*)d_in[0];
    const int*   labels   = (const int*)d_in[1];
    const int*   levels   = (const int*)d_in[2];
    float* out = (float*)d_out;

    triplet_fused_kernel<<<N, BLK>>>(features, labels, levels, out);
}

// round 9
// speedup vs baseline: 1.3377x; 1.3377x over previous
#include <cuda_runtime.h>

#define N 384
#define D 512
#define MARGIN 0.5f
#define EPS 1e-6f
#define BLK 384
#define NWARP (BLK / 32)

// Finalize scratch; zero-initialized at load, winner resets each launch so
// graph replays start clean.
__device__ float g_acc;
__device__ int   g_cnt;

__global__ __launch_bounds__(BLK) void triplet_fused_kernel(
    const float* __restrict__ features,
    const int*   __restrict__ labels,
    const int*   __restrict__ levels,
    float*       __restrict__ out) {
    __shared__ int   s_list[N];      // [0..npos) positives, [npos..npos+nneg) negatives
    __shared__ float s_distc[N];     // distance per compacted ordinal
    __shared__ int   s_wpos[NWARP];  // per-warp positive counts
    __shared__ int   s_wneg[NWARP];  // per-warp negative counts

    const int i    = blockIdx.x;
    const int t    = threadIdx.x;
    const int wid  = t >> 5;
    const int lane = t & 31;

    const int lab_i = labels[i];     // broadcast: one L2 transaction
    const int lev_i = levels[i];
    const int lab_t = labels[t];     // coalesced
    const int lev_t = levels[t];

    const bool same   = (t != i) && (lab_t == lab_i);
    const bool is_pos = same && (lev_t == lev_i);
    const bool is_neg = same && !is_pos;

    const unsigned bal_pos = __ballot_sync(0xffffffffu, is_pos);
    const unsigned bal_neg = __ballot_sync(0xffffffffu, is_neg);
    if (lane == 0) {
        s_wpos[wid] = __popc(bal_pos);
        s_wneg[wid] = __popc(bal_neg);
    }
    __syncthreads();

    // Register prefix over 12 warp counts (paid once).
    int base_p = 0, base_n = 0, npos = 0, nneg = 0;
#pragma unroll
    for (int w = 0; w < NWARP; w++) {
        const int cp = s_wpos[w], cn = s_wneg[w];
        if (w < wid) { base_p += cp; base_n += cn; }
        npos += cp;
        nneg += cn;
    }
    if (is_pos) s_list[base_p + __popc(bal_pos & ((1u << lane) - 1u))] = t;
    if (is_neg) s_list[npos + base_n + __popc(bal_neg & ((1u << lane) - 1u))] = t;
    __syncthreads();

    // ---- distances: warps round-robin over the compacted list (balanced) ----
    const int nsame = npos + nneg;
    const float4* __restrict__ fi = (const float4*)(features + i * D);
    for (int m = wid; m < nsame; m += NWARP) {
        const int j = s_list[m];
        const float4* __restrict__ fj = (const float4*)(features + j * D);
        float acc = 0.0f;
#pragma unroll
        for (int u = 0; u < 4; u++) {
            const int idx = u * 32 + lane;   // coalesced per warp, MLP=4
            float4 a = fi[idx];
            float4 b = fj[idx];
            float d0 = a.x - b.x + EPS;      // torch pairwise_distance eps
            float d1 = a.y - b.y + EPS;
            float d2 = a.z - b.z + EPS;
            float d3 = a.w - b.w + EPS;
            acc = fmaf(d0, d0, acc);
            acc = fmaf(d1, d1, acc);
            acc = fmaf(d2, d2, acc);
            acc = fmaf(d3, d3, acc);
        }
#pragma unroll
        for (int o = 16; o; o >>= 1) acc += __shfl_xor_sync(0xffffffffu, acc, o);
        if (lane == 0) s_distc[m] = sqrtf(acc);
    }
    __syncthreads();

    // ---- warp 0: full hinge (npos*nneg terms, lane-strided) + finalize ----
    if (wid == 0) {
        float acc = 0.0f;
        const int npair = npos * nneg;
        for (int p = lane; p < npair; p += 32) {
            const int a = p / nneg;          // positive ordinal
            const int q = p - a * nneg;      // negative ordinal
            acc += fmaxf(s_distc[a] - s_distc[npos + q] + MARGIN, 0.0f);
        }
#pragma unroll
        for (int o = 16; o; o >>= 1) acc += __shfl_xor_sync(0xffffffffu, acc, o);

        if (lane == 0) {
            float contrib = 0.0f;
            if (npair > 0) contrib = acc / (float)npair * (1.0f / (float)N);
            atomicAdd(&g_acc, contrib);      // no return -> REDG
            __threadfence();
            if (atomicAdd(&g_cnt, 1) == (int)gridDim.x - 1) {
                g_cnt = 0;
                out[0] = atomicExch(&g_acc, 0.0f);  // read + reset for replay
            }
        }
    }
}

extern "C" void kernel_launch(void* const* d_in, const int* in_sizes, int n_in,
                              void* d_out, int out_size) {
    const float* features = (const float*)d_in[0];
    const int*   labels   = (const int*)d_in[1];
    const int*   levels   = (const int*)d_in[2];
    float* out = (float*)d_out;

    triplet_fused_kernel<<<N, BLK>>>(features, labels, levels, out);
}

// round 10
// speedup vs baseline: 1.4624x; 1.0932x over previous
#include <cuda_runtime.h>

#define N 384
#define D 512
#define MARGIN 0.5f
#define EPS 1e-6f
#define BLK 384
#define NWARP (BLK / 32)

// Finalize scratch; zero-initialized at load, winner resets each launch so
// graph replays start clean.
__device__ float g_acc;
__device__ int   g_cnt;

__global__ __launch_bounds__(BLK) void triplet_fused_kernel(
    const float* __restrict__ features,
    const int*   __restrict__ labels,
    const int*   __restrict__ levels,
    float*       __restrict__ out) {
    __shared__ int   s_list[N];      // [0..npos) positives, [npos..npos+nneg) negatives
    __shared__ float s_distc[N];     // distance per compacted ordinal
    __shared__ int   s_wpos[NWARP];  // per-warp positive counts
    __shared__ int   s_wneg[NWARP];  // per-warp negative counts

    const int i    = blockIdx.x;
    const int t    = threadIdx.x;
    const int wid  = t >> 5;
    const int lane = t & 31;

    // Anchor row -> registers FIRST: overlaps this ~600-cycle fetch with the
    // label loads, ballots and both compaction barriers. Same address across
    // warps -> L1 broadcast, negligible extra queue pressure.
    const float4* __restrict__ fi = (const float4*)(features + i * D);
    const float4 a0 = fi[lane];
    const float4 a1 = fi[32 + lane];
    const float4 a2 = fi[64 + lane];
    const float4 a3 = fi[96 + lane];

    const int lab_i = labels[i];     // broadcast: one L2 transaction
    const int lev_i = levels[i];
    const int lab_t = labels[t];     // coalesced
    const int lev_t = levels[t];

    const bool same   = (t != i) && (lab_t == lab_i);
    const bool is_pos = same && (lev_t == lev_i);
    const bool is_neg = same && !is_pos;

    const unsigned bal_pos = __ballot_sync(0xffffffffu, is_pos);
    const unsigned bal_neg = __ballot_sync(0xffffffffu, is_neg);
    if (lane == 0) {
        s_wpos[wid] = __popc(bal_pos);
        s_wneg[wid] = __popc(bal_neg);
    }
    __syncthreads();

    // Register prefix over 12 warp counts (paid once).
    int base_p = 0, base_n = 0, npos = 0, nneg = 0;
#pragma unroll
    for (int w = 0; w < NWARP; w++) {
        const int cp = s_wpos[w], cn = s_wneg[w];
        if (w < wid) { base_p += cp; base_n += cn; }
        npos += cp;
        nneg += cn;
    }
    if (is_pos) s_list[base_p + __popc(bal_pos & ((1u << lane) - 1u))] = t;
    if (is_neg) s_list[npos + base_n + __popc(bal_neg & ((1u << lane) - 1u))] = t;
    __syncthreads();

    // ---- distances: warps round-robin over the compacted list (balanced) ----
    const int nsame = npos + nneg;
    for (int m = wid; m < nsame; m += NWARP) {
        const int j = s_list[m];
        const float4* __restrict__ fj = (const float4*)(features + j * D);
        const float4 b0 = fj[lane];
        const float4 b1 = fj[32 + lane];
        const float4 b2 = fj[64 + lane];
        const float4 b3 = fj[96 + lane];

        float acc = 0.0f, d;
        d = a0.x - b0.x + EPS; acc = fmaf(d, d, acc);   // torch eps convention
        d = a0.y - b0.y + EPS; acc = fmaf(d, d, acc);
        d = a0.z - b0.z + EPS; acc = fmaf(d, d, acc);
        d = a0.w - b0.w + EPS; acc = fmaf(d, d, acc);
        d = a1.x - b1.x + EPS; acc = fmaf(d, d, acc);
        d = a1.y - b1.y + EPS; acc = fmaf(d, d, acc);
        d = a1.z - b1.z + EPS; acc = fmaf(d, d, acc);
        d = a1.w - b1.w + EPS; acc = fmaf(d, d, acc);
        d = a2.x - b2.x + EPS; acc = fmaf(d, d, acc);
        d = a2.y - b2.y + EPS; acc = fmaf(d, d, acc);
        d = a2.z - b2.z + EPS; acc = fmaf(d, d, acc);
        d = a2.w - b2.w + EPS; acc = fmaf(d, d, acc);
        d = a3.x - b3.x + EPS; acc = fmaf(d, d, acc);
        d = a3.y - b3.y + EPS; acc = fmaf(d, d, acc);
        d = a3.z - b3.z + EPS; acc = fmaf(d, d, acc);
        d = a3.w - b3.w + EPS; acc = fmaf(d, d, acc);
#pragma unroll
        for (int o = 16; o; o >>= 1) acc += __shfl_xor_sync(0xffffffffu, acc, o);
        if (lane == 0) s_distc[m] = sqrtf(acc);
    }
    __syncthreads();

    // ---- warp 0: full hinge (npos*nneg terms, lane-strided) + finalize ----
    if (wid == 0) {
        float acc = 0.0f;
        const int npair = npos * nneg;
        for (int p = lane; p < npair; p += 32) {
            const int a = p / nneg;          // positive ordinal
            const int q = p - a * nneg;      // negative ordinal
            acc += fmaxf(s_distc[a] - s_distc[npos + q] + MARGIN, 0.0f);
        }
#pragma unroll
        for (int o = 16; o; o >>= 1) acc += __shfl_xor_sync(0xffffffffu, acc, o);

        if (lane == 0) {
            float contrib = 0.0f;
            if (npair > 0) contrib = acc / (float)npair * (1.0f / (float)N);
            atomicAdd(&g_acc, contrib);      // no return -> REDG
            __threadfence();
            if (atomicAdd(&g_cnt, 1) == (int)gridDim.x - 1) {
                g_cnt = 0;
                out[0] = atomicExch(&g_acc, 0.0f);  // read + reset for replay
            }
        }
    }
}

extern "C" void kernel_launch(void* const* d_in, const int* in_sizes, int n_in,
                              void* d_out, int out_size) {
    const float* features = (const float*)d_in[0];
    const int*   labels   = (const int*)d_in[1];
    const int*   levels   = (const int*)d_in[2];
    float* out = (float*)d_out;

    triplet_fused_kernel<<<N, BLK>>>(features, labels, levels, out);
}